// round 1
// baseline (speedup 1.0000x reference)
#include <cuda_runtime.h>
#include <cstdint>

// Problem: loss = sum_m mean(((G_t - G_m)/T)^2), G = normalized-rows Gram.
// Identity: N^2 * mean = ||M_tt||F^2 - 2||M_tm||F^2 + ||M_mm||F^2, M_ab = A^T B (512x512, K=4096).
// => 7 small GEMMs, fully L2-resident, single-scalar output.

#define NR 4096
#define DD 512

__device__ float g_norm[4][NR * DD];
__device__ float g_acc;

// ---------------- packed f32x2 helpers ----------------
__device__ __forceinline__ void ffma2(unsigned long long& acc, unsigned long long a,
                                      unsigned long long b) {
    asm("fma.rn.f32x2 %0, %1, %2, %0;" : "+l"(acc) : "l"(a), "l"(b));
}
__device__ __forceinline__ unsigned long long splat2(float x) {
    unsigned long long r;
    asm("mov.b64 %0, {%1, %1};" : "=l"(r) : "f"(x));
    return r;
}
__device__ __forceinline__ float sq2(unsigned long long p) {
    float lo, hi;
    asm("mov.b64 {%0, %1}, %2;" : "=f"(lo), "=f"(hi) : "l"(p));
    return lo * lo + hi * hi;
}

// ---------------- init / finalize ----------------
__global__ void init_kernel() { g_acc = 0.0f; }

__global__ void finalize_kernel(float* out) {
    // inv_t^2 = 100, mean over N^2 = 4096^2
    out[0] = g_acc * (100.0f / (4096.0f * 4096.0f));
}

// ---------------- row L2-normalize ----------------
// grid (4096, 4), 128 threads; each thread handles one float4 of a 512-wide row.
__global__ void normalize_kernel(const float* __restrict__ i0, const float* __restrict__ i1,
                                 const float* __restrict__ i2, const float* __restrict__ i3) {
    const float* ins[4] = {i0, i1, i2, i3};
    const float* in = ins[blockIdx.y];
    float* out = g_norm[blockIdx.y];

    int row = blockIdx.x;
    const float4* src = (const float4*)(in + (size_t)row * DD);
    float4 v = src[threadIdx.x];
    float s = v.x * v.x + v.y * v.y + v.z * v.z + v.w * v.w;
#pragma unroll
    for (int o = 16; o; o >>= 1) s += __shfl_xor_sync(0xffffffffu, s, o);
    __shared__ float ws[4];
    if ((threadIdx.x & 31) == 0) ws[threadIdx.x >> 5] = s;
    __syncthreads();
    s = ws[0] + ws[1] + ws[2] + ws[3];
    float r = rsqrtf(fmaxf(s, 1e-24f));
    float4 o4;
    o4.x = v.x * r; o4.y = v.y * r; o4.z = v.z * r; o4.w = v.w * r;
    ((float4*)(out + (size_t)row * DD))[threadIdx.x] = o4;
}

// ---------------- fused GEMM + Frobenius ----------------
// grid (8, 8, 7): 64x64 output tile of M = A^T B, K=4096, per-task weight.
// 256 threads (16x16), thread tile 4 rows x 4 cols (2 packed f32x2 col-pairs).
__global__ void __launch_bounds__(256, 2) gram_fro_kernel() {
    const int ta[7] = {3, 0, 1, 2, 3, 3, 3};
    const int tb[7] = {3, 0, 1, 2, 0, 1, 2};
    const float tw[7] = {3.0f, 1.0f, 1.0f, 1.0f, -2.0f, -2.0f, -2.0f};

    const int task = blockIdx.z;
    const float* __restrict__ A = g_norm[ta[task]];
    const float* __restrict__ B = g_norm[tb[task]];
    const int I = blockIdx.x * 64;
    const int J = blockIdx.y * 64;

    __shared__ float As[32][64];
    __shared__ float Bs[32][64];

    const int tid = threadIdx.x;
    const int tx = tid & 15;   // output col group
    const int ty = tid >> 4;   // output row group

    // load mapping: 32 rows x 16 float4-cols per tile, 2 rows per thread
    const int lrow = tid >> 4;         // 0..15
    const int lcol = (tid & 15) * 4;   // 0..60

    const float* Ag0 = A + (size_t)lrow * DD + I + lcol;
    const float* Ag1 = Ag0 + 16 * DD;
    const float* Bg0 = B + (size_t)lrow * DD + J + lcol;
    const float* Bg1 = Bg0 + 16 * DD;

    unsigned long long acc[4][2];
#pragma unroll
    for (int i = 0; i < 4; ++i) {
        acc[i][0] = 0ull;
        acc[i][1] = 0ull;
    }

    // prefetch first k-block
    float4 ra0 = *(const float4*)Ag0;
    float4 ra1 = *(const float4*)Ag1;
    float4 rb0 = *(const float4*)Bg0;
    float4 rb1 = *(const float4*)Bg1;

    for (int kb = 0; kb < 128; ++kb) {
        *(float4*)&As[lrow][lcol] = ra0;
        *(float4*)&As[lrow + 16][lcol] = ra1;
        *(float4*)&Bs[lrow][lcol] = rb0;
        *(float4*)&Bs[lrow + 16][lcol] = rb1;
        __syncthreads();

        if (kb != 127) {  // prefetch next k-block (latency hidden under compute)
            Ag0 += 32 * DD; Ag1 += 32 * DD; Bg0 += 32 * DD; Bg1 += 32 * DD;
            ra0 = *(const float4*)Ag0;
            ra1 = *(const float4*)Ag1;
            rb0 = *(const float4*)Bg0;
            rb1 = *(const float4*)Bg1;
        }

#pragma unroll
        for (int k = 0; k < 32; ++k) {
            float4 av = *(const float4*)&As[k][ty * 4];
            const unsigned long long* bp = (const unsigned long long*)&Bs[k][tx * 4];
            unsigned long long b01 = bp[0];
            unsigned long long b23 = bp[1];
            unsigned long long ap;
            ap = splat2(av.x); ffma2(acc[0][0], ap, b01); ffma2(acc[0][1], ap, b23);
            ap = splat2(av.y); ffma2(acc[1][0], ap, b01); ffma2(acc[1][1], ap, b23);
            ap = splat2(av.z); ffma2(acc[2][0], ap, b01); ffma2(acc[2][1], ap, b23);
            ap = splat2(av.w); ffma2(acc[3][0], ap, b01); ffma2(acc[3][1], ap, b23);
        }
        __syncthreads();
    }

    // per-thread sum of squares of its 4x4 M entries
    float s = 0.0f;
#pragma unroll
    for (int i = 0; i < 4; ++i) {
        s += sq2(acc[i][0]);
        s += sq2(acc[i][1]);
    }
#pragma unroll
    for (int o = 16; o; o >>= 1) s += __shfl_xor_sync(0xffffffffu, s, o);

    __shared__ float red[8];
    if ((tid & 31) == 0) red[tid >> 5] = s;
    __syncthreads();
    if (tid == 0) {
        float bs = red[0];
#pragma unroll
        for (int w = 1; w < 8; ++w) bs += red[w];
        atomicAdd(&g_acc, tw[task] * bs);
    }
}

extern "C" void kernel_launch(void* const* d_in, const int* in_sizes, int n_in,
                              void* d_out, int out_size) {
    const float* rgb   = (const float*)d_in[0];
    const float* depth = (const float*)d_in[1];
    const float* ir    = (const float*)d_in[2];
    const float* t     = (const float*)d_in[3];
    float* out = (float*)d_out;

    init_kernel<<<1, 1>>>();
    normalize_kernel<<<dim3(NR, 4, 1), 128>>>(rgb, depth, ir, t);
    gram_fro_kernel<<<dim3(8, 8, 7), 256>>>();
    finalize_kernel<<<1, 1>>>(out);
}

// round 5
// speedup vs baseline: 1.7893x; 1.7893x over previous
#include <cuda_runtime.h>
#include <cuda_bf16.h>
#include <cstdint>

// loss = sum_m mean(((G_t - G_m)/T)^2), G = Gram of row-normalized X.
// N^2/invT^2 * loss_m = ||M_tt||F^2 - 2||M_tm||F^2 + ||M_mm||F^2,  M_ab = A^T B (512x512, K=4096).
// bf16 hi/lo split concatenated along K (K=8192) makes each M one exact-ish bf16 GEMM.
// Tensor path: mma.sync.m16n8k16 (HMMA) — tcgen05 is unavailable at the harness's compute_103 target.

#define NROW 4096
#define DDIM 512
#define KTOT 8192            // hi (0..4095) || lo (4096..8191)
#define KHALF 4096           // per thread-group
#define NKB 64               // kblocks of 64 bf16 per group
#define NSTG 3
#define STG_B 32768          // A(16KB) + B(16KB) per stage
#define SMEM_DYN (2 * NSTG * STG_B + 1024)

__device__ float g_rinv[4][NROW];
__device__ __nv_bfloat16 g_tp[4][(size_t)DDIM * KTOT]; // [d][k], K-major
__device__ float g_acc;

// ---------------- PTX helpers (all valid at base sm_103) ----------------
__device__ __forceinline__ uint32_t s2u(const void* p) {
    uint32_t a;
    asm("{ .reg .u64 t; cvta.to.shared.u64 t, %1; cvt.u32.u64 %0, t; }" : "=r"(a) : "l"(p));
    return a;
}
__device__ __forceinline__ void cp16(uint32_t dst, const void* src) {
    asm volatile("cp.async.cg.shared.global [%0], [%1], 16;" :: "r"(dst), "l"(src) : "memory");
}
#define CP_COMMIT() asm volatile("cp.async.commit_group;" ::: "memory")
#define CP_WAIT(n)  asm volatile("cp.async.wait_group %0;" :: "n"(n) : "memory")
#define BARG(id)    asm volatile("bar.sync %0, 128;" :: "r"(id) : "memory")

__device__ __forceinline__ void ldsm4(uint32_t* r, uint32_t addr) {
    asm volatile("ldmatrix.sync.aligned.m8n8.x4.shared.b16 {%0,%1,%2,%3}, [%4];"
                 : "=r"(r[0]), "=r"(r[1]), "=r"(r[2]), "=r"(r[3]) : "r"(addr));
}
__device__ __forceinline__ void mma16816(float* d, const uint32_t* a, const uint32_t* b) {
    asm volatile(
        "mma.sync.aligned.m16n8k16.row.col.f32.bf16.bf16.f32 "
        "{%0,%1,%2,%3}, {%4,%5,%6,%7}, {%8,%9}, {%0,%1,%2,%3};"
        : "+f"(d[0]), "+f"(d[1]), "+f"(d[2]), "+f"(d[3])
        : "r"(a[0]), "r"(a[1]), "r"(a[2]), "r"(a[3]), "r"(b[0]), "r"(b[1]));
}

// ---------------- small kernels ----------------
__global__ void init_kernel() { g_acc = 0.0f; }
__global__ void finalize_kernel(float* out) {
    out[0] = g_acc * (100.0f / (4096.0f * 4096.0f));
}

// per-row inverse L2 norm: grid (4096, 4), 128 threads
__global__ void rinv_kernel(const float* __restrict__ i0, const float* __restrict__ i1,
                            const float* __restrict__ i2, const float* __restrict__ i3) {
    const float* ins[4] = {i0, i1, i2, i3};
    const float* in = ins[blockIdx.y];
    int row = blockIdx.x;
    float4 v = ((const float4*)(in + (size_t)row * DDIM))[threadIdx.x];
    float s = v.x * v.x + v.y * v.y + v.z * v.z + v.w * v.w;
#pragma unroll
    for (int o = 16; o; o >>= 1) s += __shfl_xor_sync(0xffffffffu, s, o);
    __shared__ float ws[4];
    if ((threadIdx.x & 31) == 0) ws[threadIdx.x >> 5] = s;
    __syncthreads();
    if (threadIdx.x == 0) {
        float t = ws[0] + ws[1] + ws[2] + ws[3];
        g_rinv[blockIdx.y][row] = rsqrtf(fmaxf(t, 1e-24f));
    }
}

// transpose + normalize + bf16 hi/lo split: grid (4096/32, 512/128, 4), 256 threads
__global__ void tconv_kernel(const float* __restrict__ i0, const float* __restrict__ i1,
                             const float* __restrict__ i2, const float* __restrict__ i3) {
    const float* ins[4] = {i0, i1, i2, i3};
    int mod = blockIdx.z;
    const float* in = ins[mod];
    __nv_bfloat16* out = g_tp[mod];
    int r0 = blockIdx.x * 32, ib = blockIdx.y * 128;

    __shared__ float tile[32][132];
    int tx = threadIdx.x & 31, ty = threadIdx.x >> 5;
#pragma unroll
    for (int rr = ty; rr < 32; rr += 8) {
        float4 v = *(const float4*)(in + (size_t)(r0 + rr) * DDIM + ib + tx * 4);
        float rv = g_rinv[mod][r0 + rr];
        tile[rr][tx * 4 + 0] = v.x * rv;
        tile[rr][tx * 4 + 1] = v.y * rv;
        tile[rr][tx * 4 + 2] = v.z * rv;
        tile[rr][tx * 4 + 3] = v.w * rv;
    }
    __syncthreads();

    int il = threadIdx.x >> 1;
    int rs = (threadIdx.x & 1) * 16;
    __align__(16) __nv_bfloat16 hi[16], lo[16];
#pragma unroll
    for (int j = 0; j < 16; ++j) {
        float v = tile[rs + j][il];
        __nv_bfloat16 h = __float2bfloat16(v);
        hi[j] = h;
        lo[j] = __float2bfloat16(v - __bfloat162float(h));
    }
    size_t ob = (size_t)(ib + il) * KTOT + r0 + rs;
    *(uint4*)(out + ob) = *(const uint4*)&hi[0];
    *(uint4*)(out + ob + 8) = *(const uint4*)&hi[8];
    *(uint4*)(out + ob + 4096) = *(const uint4*)&lo[0];
    *(uint4*)(out + ob + 4096 + 8) = *(const uint4*)&lo[8];
}

// ---------------- HMMA GEMM + Frobenius ----------------
// grid (4,4,7), 256 threads. Two 128-thread groups K-split (4096 each).
// Group: 4 warps, 2x2 arrangement, 64x64 warp tile of the 128x128 CTA tile.
__global__ void __launch_bounds__(256, 1) gemmfro_kernel() {
    const int ta[7] = {3, 0, 1, 2, 3, 3, 3};
    const int tb[7] = {3, 0, 1, 2, 0, 1, 2};
    const float tw[7] = {3.0f, 1.0f, 1.0f, 1.0f, -2.0f, -2.0f, -2.0f};

    extern __shared__ __align__(16) char dsm[];
    __shared__ float red[8];

    const int tid = threadIdx.x;
    const int wid = tid >> 5;
    const int g = wid >> 2;           // k-split group 0/1
    const int wq = wid & 3;           // warp quadrant within group
    const int lane = tid & 31;
    const int l = tid & 127;          // group-local thread id

    uint32_t smem0 = (s2u(dsm) + 1023u) & ~1023u;
    uint32_t gbase = smem0 + (uint32_t)g * (NSTG * STG_B);

    const int task = blockIdx.z;
    const __nv_bfloat16* A = g_tp[ta[task]];
    const __nv_bfloat16* B = g_tp[tb[task]];
    const int I = blockIdx.x * 128;
    const int J = blockIdx.y * 128;

    // ---- cp.async source rows (one 128-byte row per group-local thread) ----
    const char* aRow = (const char*)(A + (size_t)(I + l) * KTOT + (size_t)g * KHALF);
    const char* bRow = (const char*)(B + (size_t)(J + l) * KTOT + (size_t)g * KHALF);
    uint32_t so[8];
#pragma unroll
    for (int c = 0; c < 8; ++c) so[c] = (uint32_t)l * 128 + (uint32_t)((c * 16) ^ ((l & 7) * 16));

    // ---- ldmatrix lane address precompute ----
    const int m0 = (wq & 1) * 64, n0 = (wq >> 1) * 64;
    uint32_t aoff[4], axr[4], boff[4], bxr[4];
#pragma unroll
    for (int i = 0; i < 4; ++i) {
        int r = m0 + i * 16 + ((lane >> 3) & 1) * 8 + (lane & 7);
        aoff[i] = (uint32_t)r * 128;
        axr[i] = (uint32_t)(r & 7) * 16;
    }
#pragma unroll
    for (int jp = 0; jp < 4; ++jp) {
        int r = n0 + jp * 16 + ((lane >> 4) & 1) * 8 + (lane & 7);
        boff[jp] = (uint32_t)r * 128;
        bxr[jp] = (uint32_t)(r & 7) * 16;
    }
    const uint32_t ah = (uint32_t)(lane >> 4) * 16;
    const uint32_t bh = (uint32_t)((lane >> 3) & 1) * 16;

    float acc[4][8][4];
#pragma unroll
    for (int i = 0; i < 4; ++i)
#pragma unroll
        for (int j = 0; j < 8; ++j)
#pragma unroll
            for (int r = 0; r < 4; ++r) acc[i][j][r] = 0.0f;

    auto load_stage = [&](int kb) {
        uint32_t as = gbase + (uint32_t)(kb % NSTG) * STG_B;
        uint32_t bs = as + 16384;
        const char* ag = aRow + (size_t)kb * 128;
        const char* bg = bRow + (size_t)kb * 128;
#pragma unroll
        for (int c = 0; c < 8; ++c) cp16(as + so[c], ag + c * 16);
#pragma unroll
        for (int c = 0; c < 8; ++c) cp16(bs + so[c], bg + c * 16);
    };

    load_stage(0); CP_COMMIT();
    load_stage(1); CP_COMMIT();

    for (int kb = 0; kb < NKB; ++kb) {
        CP_WAIT(1);
        BARG(g + 1);                        // group-wide: stage kb visible, stage kb-1 free
        if (kb + 2 < NKB) load_stage(kb + 2);
        CP_COMMIT();

        uint32_t sa = gbase + (uint32_t)(kb % NSTG) * STG_B;
        uint32_t sb = sa + 16384;
#pragma unroll
        for (int ks = 0; ks < 4; ++ks) {
            uint32_t af[4][4], bf[4][4];
            uint32_t ko = (uint32_t)(ks * 32);
#pragma unroll
            for (int i = 0; i < 4; ++i) ldsm4(af[i], sa + aoff[i] + ((ko + ah) ^ axr[i]));
#pragma unroll
            for (int jp = 0; jp < 4; ++jp) ldsm4(bf[jp], sb + boff[jp] + ((ko + bh) ^ bxr[jp]));
#pragma unroll
            for (int i = 0; i < 4; ++i)
#pragma unroll
                for (int jp = 0; jp < 4; ++jp) {
                    mma16816(acc[i][2 * jp + 0], af[i], &bf[jp][0]);
                    mma16816(acc[i][2 * jp + 1], af[i], &bf[jp][2]);
                }
        }
    }

    // ---- combine k-halves exactly, then square ----
    __syncthreads();
    float* xch = (float*)dsm;               // stride 129 => conflict-free
    const float* accf = &acc[0][0][0];
    if (g == 1) {
        float* p = xch + (size_t)l * 129;
#pragma unroll
        for (int r = 0; r < 128; ++r) p[r] = accf[r];
    }
    __syncthreads();
    float s = 0.0f;
    if (g == 0) {
        const float* p = xch + (size_t)l * 129;
#pragma unroll
        for (int r = 0; r < 128; ++r) {
            float v = accf[r] + p[r];
            s += v * v;
        }
    }
#pragma unroll
    for (int o = 16; o; o >>= 1) s += __shfl_xor_sync(0xffffffffu, s, o);
    if (lane == 0) red[wid] = s;
    __syncthreads();
    if (tid == 0) {
        float bs = red[0];
#pragma unroll
        for (int w = 1; w < 8; ++w) bs += red[w];
        atomicAdd(&g_acc, tw[task] * bs);
    }
}

extern "C" void kernel_launch(void* const* d_in, const int* in_sizes, int n_in,
                              void* d_out, int out_size) {
    const float* rgb   = (const float*)d_in[0];
    const float* depth = (const float*)d_in[1];
    const float* ir    = (const float*)d_in[2];
    const float* t     = (const float*)d_in[3];
    float* out = (float*)d_out;

    cudaFuncSetAttribute(gemmfro_kernel, cudaFuncAttributeMaxDynamicSharedMemorySize, SMEM_DYN);

    init_kernel<<<1, 1>>>();
    rinv_kernel<<<dim3(NROW, 4, 1), 128>>>(rgb, depth, ir, t);
    tconv_kernel<<<dim3(NROW / 32, DDIM / 128, 4), 256>>>(rgb, depth, ir, t);
    gemmfro_kernel<<<dim3(4, 4, 7), 256, SMEM_DYN>>>();
    finalize_kernel<<<1, 1>>>(out);
}

// round 11
// speedup vs baseline: 2.1914x; 1.2247x over previous
#include <cuda_runtime.h>
#include <cuda_bf16.h>
#include <cstdint>

// loss = sum_m mean(((G_t - G_m)/T)^2), G = Gram of row-normalized X.
// N^2/invT^2 * loss_m = ||M_tt||F^2 - 2||M_tm||F^2 + ||M_mm||F^2,  M_ab = A^T B (512x512, K=4096).
// bf16 hi/lo split concatenated along K (K=8192): each M is one bf16 GEMM, fp32 accum.
// mma.sync.m16n8k16 path (tcgen05 not available at harness's compute_103 target).

#define NROW 4096
#define DDIM 512
#define KTOT 8192            // hi (0..4095) || lo (4096..8191)
#define NKB 128              // kblocks of 64 bf16 (128 bytes)
#define NSTG 4
#define STG_B 32768          // A(16KB) + B(16KB)
#define SMEM_DYN (NSTG * STG_B + 1024)

__device__ float g_rinv[4][NROW];
__device__ __nv_bfloat16 g_tp[4][(size_t)DDIM * KTOT]; // [d][k], K-major
__device__ float g_acc;

// ---------------- PTX helpers ----------------
__device__ __forceinline__ uint32_t s2u(const void* p) {
    uint32_t a;
    asm("{ .reg .u64 t; cvta.to.shared.u64 t, %1; cvt.u32.u64 %0, t; }" : "=r"(a) : "l"(p));
    return a;
}
__device__ __forceinline__ void cp16(uint32_t dst, const void* src) {
    asm volatile("cp.async.cg.shared.global [%0], [%1], 16;" :: "r"(dst), "l"(src) : "memory");
}
#define CP_COMMIT() asm volatile("cp.async.commit_group;" ::: "memory")
#define CP_WAIT(n)  asm volatile("cp.async.wait_group %0;" :: "n"(n) : "memory")

__device__ __forceinline__ void ldsm4(uint32_t* r, uint32_t addr) {
    asm volatile("ldmatrix.sync.aligned.m8n8.x4.shared.b16 {%0,%1,%2,%3}, [%4];"
                 : "=r"(r[0]), "=r"(r[1]), "=r"(r[2]), "=r"(r[3]) : "r"(addr));
}
__device__ __forceinline__ void mma16816(float* d, const uint32_t* a, const uint32_t* b) {
    asm volatile(
        "mma.sync.aligned.m16n8k16.row.col.f32.bf16.bf16.f32 "
        "{%0,%1,%2,%3}, {%4,%5,%6,%7}, {%8,%9}, {%0,%1,%2,%3};"
        : "+f"(d[0]), "+f"(d[1]), "+f"(d[2]), "+f"(d[3])
        : "r"(a[0]), "r"(a[1]), "r"(a[2]), "r"(a[3]), "r"(b[0]), "r"(b[1]));
}

// ---------------- small kernels ----------------
__global__ void init_kernel() { g_acc = 0.0f; }
__global__ void finalize_kernel(float* out) {
    out[0] = g_acc * (100.0f / (4096.0f * 4096.0f));
}

// per-row inverse L2 norm: grid (4096, 4), 128 threads
__global__ void rinv_kernel(const float* __restrict__ i0, const float* __restrict__ i1,
                            const float* __restrict__ i2, const float* __restrict__ i3) {
    const float* ins[4] = {i0, i1, i2, i3};
    const float* in = ins[blockIdx.y];
    int row = blockIdx.x;
    float4 v = ((const float4*)(in + (size_t)row * DDIM))[threadIdx.x];
    float s = v.x * v.x + v.y * v.y + v.z * v.z + v.w * v.w;
#pragma unroll
    for (int o = 16; o; o >>= 1) s += __shfl_xor_sync(0xffffffffu, s, o);
    __shared__ float ws[4];
    if ((threadIdx.x & 31) == 0) ws[threadIdx.x >> 5] = s;
    __syncthreads();
    if (threadIdx.x == 0) {
        float t = ws[0] + ws[1] + ws[2] + ws[3];
        g_rinv[blockIdx.y][row] = rsqrtf(fmaxf(t, 1e-24f));
    }
}

// transpose + normalize + bf16 hi/lo split: grid (4096/32, 512/128, 4), 256 threads
__global__ void tconv_kernel(const float* __restrict__ i0, const float* __restrict__ i1,
                             const float* __restrict__ i2, const float* __restrict__ i3) {
    const float* ins[4] = {i0, i1, i2, i3};
    int mod = blockIdx.z;
    const float* in = ins[mod];
    __nv_bfloat16* out = g_tp[mod];
    int r0 = blockIdx.x * 32, ib = blockIdx.y * 128;

    __shared__ float tile[32][132];
    int tx = threadIdx.x & 31, ty = threadIdx.x >> 5;
#pragma unroll
    for (int rr = ty; rr < 32; rr += 8) {
        float4 v = *(const float4*)(in + (size_t)(r0 + rr) * DDIM + ib + tx * 4);
        float rv = g_rinv[mod][r0 + rr];
        tile[rr][tx * 4 + 0] = v.x * rv;
        tile[rr][tx * 4 + 1] = v.y * rv;
        tile[rr][tx * 4 + 2] = v.z * rv;
        tile[rr][tx * 4 + 3] = v.w * rv;
    }
    __syncthreads();

    int il = threadIdx.x >> 1;
    int rs = (threadIdx.x & 1) * 16;
    __align__(16) __nv_bfloat16 hi[16], lo[16];
#pragma unroll
    for (int j = 0; j < 16; ++j) {
        float v = tile[rs + j][il];
        __nv_bfloat16 h = __float2bfloat16(v);
        hi[j] = h;
        lo[j] = __float2bfloat16(v - __bfloat162float(h));
    }
    size_t ob = (size_t)(ib + il) * KTOT + r0 + rs;
    *(uint4*)(out + ob) = *(const uint4*)&hi[0];
    *(uint4*)(out + ob + 8) = *(const uint4*)&hi[8];
    *(uint4*)(out + ob + 4096) = *(const uint4*)&lo[0];
    *(uint4*)(out + ob + 4096 + 8) = *(const uint4*)&lo[8];
}

// ---------------- HMMA GEMM + Frobenius ----------------
// grid (4,4,7), 512 threads = 16 warps in a 4x4 grid, warp tile 32x32, K=8192 single stream.
__global__ void __launch_bounds__(512, 1) gemmfro_kernel() {
    const int ta[7] = {3, 0, 1, 2, 3, 3, 3};
    const int tb[7] = {3, 0, 1, 2, 0, 1, 2};
    const float tw[7] = {3.0f, 1.0f, 1.0f, 1.0f, -2.0f, -2.0f, -2.0f};

    extern __shared__ __align__(16) char dsm[];
    __shared__ float red[16];

    const int tid = threadIdx.x;
    const int wid = tid >> 5;         // 0..15
    const int lane = tid & 31;
    const int wm = wid & 3;           // warp m index
    const int wn = wid >> 2;          // warp n index

    uint32_t smem0 = (s2u(dsm) + 1023u) & ~1023u;

    const int task = blockIdx.z;
    const __nv_bfloat16* A = g_tp[ta[task]];
    const __nv_bfloat16* B = g_tp[tb[task]];
    const int I = blockIdx.x * 128;
    const int J = blockIdx.y * 128;

    // ---- cp.async mapping: 512 threads cover 256 rows x 128B; thread owns half a row ----
    const int lrow = tid >> 1;               // 0..255  (0-127: A rows, 128-255: B rows)
    const int cb = (tid & 1) * 4;            // first 16B chunk
    const __nv_bfloat16* gsrc = (lrow < 128)
        ? (A + (size_t)(I + lrow) * KTOT)
        : (B + (size_t)(J + lrow - 128) * KTOT);
    const char* srow = (const char*)gsrc;
    uint32_t soff[4];
#pragma unroll
    for (int c = 0; c < 4; ++c)
        soff[c] = (uint32_t)lrow * 128 + (uint32_t)(((cb + c) * 16) ^ ((lrow & 7) * 16));

    auto load_stage = [&](int kb) {
        uint32_t base = smem0 + (uint32_t)(kb & (NSTG - 1)) * STG_B;
        const char* g = srow + (size_t)kb * 128;
#pragma unroll
        for (int c = 0; c < 4; ++c) cp16(base + soff[c], g + (cb + c) * 16);
    };

    // ---- ldmatrix lane address precompute (warp tile 32x32) ----
    const int m0 = wm * 32, n0 = wn * 32;
    uint32_t aoff[2], axr[2], boff[2], bxr[2];
#pragma unroll
    for (int i = 0; i < 2; ++i) {
        int r = m0 + i * 16 + ((lane >> 3) & 1) * 8 + (lane & 7);
        aoff[i] = (uint32_t)r * 128;
        axr[i] = (uint32_t)(r & 7) * 16;
    }
#pragma unroll
    for (int jp = 0; jp < 2; ++jp) {
        int r = n0 + jp * 16 + ((lane >> 4) & 1) * 8 + (lane & 7);
        boff[jp] = (uint32_t)r * 128;
        bxr[jp] = (uint32_t)(r & 7) * 16;
    }
    const uint32_t ah = (uint32_t)(lane >> 4) * 16;
    const uint32_t bh = (uint32_t)((lane >> 3) & 1) * 16;

    float acc[2][4][4];
#pragma unroll
    for (int i = 0; i < 2; ++i)
#pragma unroll
        for (int j = 0; j < 4; ++j)
#pragma unroll
            for (int r = 0; r < 4; ++r) acc[i][j][r] = 0.0f;

    load_stage(0); CP_COMMIT();
    load_stage(1); CP_COMMIT();
    load_stage(2); CP_COMMIT();

    for (int kb = 0; kb < NKB; ++kb) {
        CP_WAIT(2);
        __syncthreads();                 // stage kb visible to all; stage kb-1 compute done
        if (kb + 3 < NKB) load_stage(kb + 3);
        CP_COMMIT();

        uint32_t sa = smem0 + (uint32_t)(kb & (NSTG - 1)) * STG_B;
        uint32_t sb = sa + 16384;
#pragma unroll
        for (int ks = 0; ks < 4; ++ks) {
            uint32_t af[2][4], bf[2][4];
            uint32_t ko = (uint32_t)(ks * 32);
#pragma unroll
            for (int i = 0; i < 2; ++i) ldsm4(af[i], sa + aoff[i] + ((ko + ah) ^ axr[i]));
#pragma unroll
            for (int jp = 0; jp < 2; ++jp) ldsm4(bf[jp], sb + boff[jp] + ((ko + bh) ^ bxr[jp]));
#pragma unroll
            for (int i = 0; i < 2; ++i)
#pragma unroll
                for (int jp = 0; jp < 2; ++jp) {
                    mma16816(acc[i][2 * jp + 0], af[i], &bf[jp][0]);
                    mma16816(acc[i][2 * jp + 1], af[i], &bf[jp][2]);
                }
        }
    }

    // ---- Frobenius of this warp's 32x32 block ----
    float s = 0.0f;
#pragma unroll
    for (int i = 0; i < 2; ++i)
#pragma unroll
        for (int j = 0; j < 4; ++j)
#pragma unroll
            for (int r = 0; r < 4; ++r) s += acc[i][j][r] * acc[i][j][r];
#pragma unroll
    for (int o = 16; o; o >>= 1) s += __shfl_xor_sync(0xffffffffu, s, o);
    if (lane == 0) red[wid] = s;
    __syncthreads();
    if (tid == 0) {
        float bs = red[0];
#pragma unroll
        for (int w = 1; w < 16; ++w) bs += red[w];
        atomicAdd(&g_acc, tw[task] * bs);
    }
}

extern "C" void kernel_launch(void* const* d_in, const int* in_sizes, int n_in,
                              void* d_out, int out_size) {
    const float* rgb   = (const float*)d_in[0];
    const float* depth = (const float*)d_in[1];
    const float* ir    = (const float*)d_in[2];
    const float* t     = (const float*)d_in[3];
    float* out = (float*)d_out;

    cudaFuncSetAttribute(gemmfro_kernel, cudaFuncAttributeMaxDynamicSharedMemorySize, SMEM_DYN);

    init_kernel<<<1, 1>>>();
    rinv_kernel<<<dim3(NROW, 4, 1), 128>>>(rgb, depth, ir, t);
    tconv_kernel<<<dim3(NROW / 32, DDIM / 128, 4), 256>>>(rgb, depth, ir, t);
    gemmfro_kernel<<<dim3(4, 4, 7), 512, SMEM_DYN>>>();
    finalize_kernel<<<1, 1>>>(out);
}

// round 12
// speedup vs baseline: 2.2228x; 1.0143x over previous
#include <cuda_runtime.h>
#include <cuda_bf16.h>
#include <cstdint>

// loss = sum_m mean(((G_t - G_m)/T)^2), G = Gram of row-normalized X.
// N^2/invT^2 * loss_m = ||M_tt||F^2 - 2||M_tm||F^2 + ||M_mm||F^2,  M_ab = A^T B (512x512, K=4096).
// bf16 hi/lo split concatenated along K (K=8192): each M is one bf16 GEMM, fp32 accum.
// mma.sync.m16n8k16 path (tcgen05 not available at harness's compute_103 target).

#define NROW 4096
#define DDIM 512
#define KTOT 8192            // hi (0..4095) || lo (4096..8191)
#define NKB 128              // kblocks of 64 bf16 (128 bytes)
#define NSTG 6               // ring of 6 stages, 2 kblocks consumed per sync
#define STG_B 32768          // A(16KB) + B(16KB)
#define SMEM_DYN (NSTG * STG_B + 1024)
#define PREP_SMEM (32 * 516 * 4)

__device__ float g_rinv_unused;  // (rinv fused into prep)
__device__ __nv_bfloat16 g_tp[4][(size_t)DDIM * KTOT]; // [d][k], K-major
__device__ float g_acc;

// ---------------- PTX helpers ----------------
__device__ __forceinline__ uint32_t s2u(const void* p) {
    uint32_t a;
    asm("{ .reg .u64 t; cvta.to.shared.u64 t, %1; cvt.u32.u64 %0, t; }" : "=r"(a) : "l"(p));
    return a;
}
__device__ __forceinline__ void cp16(uint32_t dst, const void* src) {
    asm volatile("cp.async.cg.shared.global [%0], [%1], 16;" :: "r"(dst), "l"(src) : "memory");
}
#define CP_COMMIT() asm volatile("cp.async.commit_group;" ::: "memory")
#define CP_WAIT(n)  asm volatile("cp.async.wait_group %0;" :: "n"(n) : "memory")

__device__ __forceinline__ void ldsm4(uint32_t* r, uint32_t addr) {
    asm volatile("ldmatrix.sync.aligned.m8n8.x4.shared.b16 {%0,%1,%2,%3}, [%4];"
                 : "=r"(r[0]), "=r"(r[1]), "=r"(r[2]), "=r"(r[3]) : "r"(addr));
}
__device__ __forceinline__ void mma16816(float* d, const uint32_t* a, const uint32_t* b) {
    asm volatile(
        "mma.sync.aligned.m16n8k16.row.col.f32.bf16.bf16.f32 "
        "{%0,%1,%2,%3}, {%4,%5,%6,%7}, {%8,%9}, {%0,%1,%2,%3};"
        : "+f"(d[0]), "+f"(d[1]), "+f"(d[2]), "+f"(d[3])
        : "r"(a[0]), "r"(a[1]), "r"(a[2]), "r"(a[3]), "r"(b[0]), "r"(b[1]));
}

// ---------------- finalize ----------------
__global__ void finalize_kernel(float* out) {
    out[0] = g_acc * (100.0f / (4096.0f * 4096.0f));
}

// ---------------- fused normalize + transpose + bf16 hi/lo split ----------------
// grid (4096/32, 4), 256 threads; block holds 32 full rows (32x512 fp32) in SMEM.
__global__ void __launch_bounds__(256, 1) prep_kernel(
    const float* __restrict__ i0, const float* __restrict__ i1,
    const float* __restrict__ i2, const float* __restrict__ i3) {
    const float* ins[4] = {i0, i1, i2, i3};
    const int mod = blockIdx.y;
    const float* in = ins[mod];
    __nv_bfloat16* out = g_tp[mod];
    const int r0 = blockIdx.x * 32;
    const int tid = threadIdx.x;

    if (blockIdx.x == 0 && mod == 0 && tid == 0) g_acc = 0.0f;

    extern __shared__ float ptile[];   // [32][516]
    __shared__ float rnorm[32];

    // load 32 rows x 512 fp32
    for (int i = tid; i < 32 * 128; i += 256) {
        int r = i >> 7, c = i & 127;
        float4 v = ((const float4*)(in + (size_t)(r0 + r) * DDIM))[c];
        *(float4*)&ptile[r * 516 + c * 4] = v;
    }
    __syncthreads();

    // per-row inverse L2 norm: warp w handles rows w, w+8, w+16, w+24
    {
        int w = tid >> 5, lane = tid & 31;
        for (int r = w; r < 32; r += 8) {
            const float* row = &ptile[r * 516];
            float s = 0.0f;
#pragma unroll
            for (int k = 0; k < 16; ++k) {
                float v = row[lane + 32 * k];
                s += v * v;
            }
#pragma unroll
            for (int o = 16; o; o >>= 1) s += __shfl_xor_sync(0xffffffffu, s, o);
            if (lane == 0) rnorm[r] = rsqrtf(fmaxf(s, 1e-24f));
        }
    }
    __syncthreads();

    // transpose + hi/lo split, 4 chunks of 128 cols
    const int il = tid >> 1;            // 0..127
    const int rs = (tid & 1) * 16;      // row 0..15 or 16..31
    for (int c4 = 0; c4 < 4; ++c4) {
        const int ib = c4 * 128;
        __align__(16) __nv_bfloat16 hi[16], lo[16];
#pragma unroll
        for (int j = 0; j < 16; ++j) {
            float v = ptile[(rs + j) * 516 + ib + il] * rnorm[rs + j];
            __nv_bfloat16 h = __float2bfloat16(v);
            hi[j] = h;
            lo[j] = __float2bfloat16(v - __bfloat162float(h));
        }
        size_t ob = (size_t)(ib + il) * KTOT + r0 + rs;
        *(uint4*)(out + ob) = *(const uint4*)&hi[0];
        *(uint4*)(out + ob + 8) = *(const uint4*)&hi[8];
        *(uint4*)(out + ob + 4096) = *(const uint4*)&lo[0];
        *(uint4*)(out + ob + 4096 + 8) = *(const uint4*)&lo[8];
    }
}

// ---------------- HMMA GEMM + Frobenius ----------------
// grid (4,4,7), 512 threads = 16 warps (4x4), warp tile 32x32.
// 6-stage ring, 2 kblocks consumed per __syncthreads.
__global__ void __launch_bounds__(512, 1) gemmfro_kernel() {
    const int ta[7] = {3, 0, 1, 2, 3, 3, 3};
    const int tb[7] = {3, 0, 1, 2, 0, 1, 2};
    const float tw[7] = {3.0f, 1.0f, 1.0f, 1.0f, -2.0f, -2.0f, -2.0f};

    extern __shared__ __align__(16) char dsm[];
    __shared__ float red[16];

    const int tid = threadIdx.x;
    const int wid = tid >> 5;
    const int lane = tid & 31;
    const int wm = wid & 3;
    const int wn = wid >> 2;

    uint32_t smem0 = (s2u(dsm) + 1023u) & ~1023u;

    const int task = blockIdx.z;
    const __nv_bfloat16* A = g_tp[ta[task]];
    const __nv_bfloat16* B = g_tp[tb[task]];
    const int I = blockIdx.x * 128;
    const int J = blockIdx.y * 128;

    // cp.async mapping: 512 threads cover 256 rows x 128B; thread owns half a row
    const int lrow = tid >> 1;
    const int cb = (tid & 1) * 4;
    const __nv_bfloat16* gsrc = (lrow < 128)
        ? (A + (size_t)(I + lrow) * KTOT)
        : (B + (size_t)(J + lrow - 128) * KTOT);
    const char* srow = (const char*)gsrc;
    uint32_t soff[4];
#pragma unroll
    for (int c = 0; c < 4; ++c)
        soff[c] = (uint32_t)lrow * 128 + (uint32_t)(((cb + c) * 16) ^ ((lrow & 7) * 16));

    auto load_stage = [&](int kb) {
        uint32_t base = smem0 + (uint32_t)(kb % NSTG) * STG_B;
        const char* g = srow + (size_t)kb * 128;
#pragma unroll
        for (int c = 0; c < 4; ++c) cp16(base + soff[c], g + (cb + c) * 16);
    };

    // ldmatrix lane address precompute (warp tile 32x32)
    const int m0 = wm * 32, n0 = wn * 32;
    uint32_t aoff[2], axr[2], boff[2], bxr[2];
#pragma unroll
    for (int i = 0; i < 2; ++i) {
        int r = m0 + i * 16 + ((lane >> 3) & 1) * 8 + (lane & 7);
        aoff[i] = (uint32_t)r * 128;
        axr[i] = (uint32_t)(r & 7) * 16;
    }
#pragma unroll
    for (int jp = 0; jp < 2; ++jp) {
        int r = n0 + jp * 16 + ((lane >> 4) & 1) * 8 + (lane & 7);
        boff[jp] = (uint32_t)r * 128;
        bxr[jp] = (uint32_t)(r & 7) * 16;
    }
    const uint32_t ah = (uint32_t)(lane >> 4) * 16;
    const uint32_t bh = (uint32_t)((lane >> 3) & 1) * 16;

    float acc[2][4][4];
#pragma unroll
    for (int i = 0; i < 2; ++i)
#pragma unroll
        for (int j = 0; j < 4; ++j)
#pragma unroll
            for (int r = 0; r < 4; ++r) acc[i][j][r] = 0.0f;

    auto compute_kb = [&](int kb) {
        uint32_t sa = smem0 + (uint32_t)(kb % NSTG) * STG_B;
        uint32_t sb = sa + 16384;
#pragma unroll
        for (int ks = 0; ks < 4; ++ks) {
            uint32_t af[2][4], bf[2][4];
            uint32_t ko = (uint32_t)(ks * 32);
#pragma unroll
            for (int i = 0; i < 2; ++i) ldsm4(af[i], sa + aoff[i] + ((ko + ah) ^ axr[i]));
#pragma unroll
            for (int jp = 0; jp < 2; ++jp) ldsm4(bf[jp], sb + boff[jp] + ((ko + bh) ^ bxr[jp]));
#pragma unroll
            for (int i = 0; i < 2; ++i)
#pragma unroll
                for (int jp = 0; jp < 2; ++jp) {
                    mma16816(acc[i][2 * jp + 0], af[i], &bf[jp][0]);
                    mma16816(acc[i][2 * jp + 1], af[i], &bf[jp][2]);
                }
        }
    };

    // prologue: 4 stages in flight
    load_stage(0); CP_COMMIT();
    load_stage(1); CP_COMMIT();
    load_stage(2); CP_COMMIT();
    load_stage(3); CP_COMMIT();

    for (int kb = 0; kb < NKB; kb += 2) {
        CP_WAIT(2);                 // stages kb, kb+1 resident (kb+2, kb+3 may be in flight)
        __syncthreads();            // all warps done with stages kb-2, kb-1 (slots being reloaded)
        if (kb + 4 < NKB) { load_stage(kb + 4); CP_COMMIT(); }
        if (kb + 5 < NKB) { load_stage(kb + 5); CP_COMMIT(); }
        compute_kb(kb);
        compute_kb(kb + 1);
    }

    // Frobenius of this warp's 32x32 block
    float s = 0.0f;
#pragma unroll
    for (int i = 0; i < 2; ++i)
#pragma unroll
        for (int j = 0; j < 4; ++j)
#pragma unroll
            for (int r = 0; r < 4; ++r) s += acc[i][j][r] * acc[i][j][r];
#pragma unroll
    for (int o = 16; o; o >>= 1) s += __shfl_xor_sync(0xffffffffu, s, o);
    if (lane == 0) red[wid] = s;
    __syncthreads();
    if (tid == 0) {
        float bs = red[0];
#pragma unroll
        for (int w = 1; w < 16; ++w) bs += red[w];
        atomicAdd(&g_acc, tw[task] * bs);
    }
}

extern "C" void kernel_launch(void* const* d_in, const int* in_sizes, int n_in,
                              void* d_out, int out_size) {
    const float* rgb   = (const float*)d_in[0];
    const float* depth = (const float*)d_in[1];
    const float* ir    = (const float*)d_in[2];
    const float* t     = (const float*)d_in[3];
    float* out = (float*)d_out;

    cudaFuncSetAttribute(prep_kernel, cudaFuncAttributeMaxDynamicSharedMemorySize, PREP_SMEM);
    cudaFuncSetAttribute(gemmfro_kernel, cudaFuncAttributeMaxDynamicSharedMemorySize, SMEM_DYN);

    prep_kernel<<<dim3(NROW / 32, 4, 1), 256, PREP_SMEM>>>(rgb, depth, ir, t);
    gemmfro_kernel<<<dim3(4, 4, 7), 512, SMEM_DYN>>>();
    finalize_kernel<<<1, 1>>>(out);
}

// round 17
// speedup vs baseline: 2.4179x; 1.0878x over previous
#include <cuda_runtime.h>
#include <cuda_bf16.h>
#include <cstdint>

// loss = sum_m mean(((G_t - G_m)/T)^2), G = Gram of row-normalized X.
// N^2/invT^2 * loss_m = ||M_tt||F^2 - 2||M_tm||F^2 + ||M_mm||F^2,  M_ab = A^T B (512x512, K=4096).
// bf16 hi/lo split concatenated along K (K=8192): each M is one bf16 GEMM, fp32 accum.
// mma.sync.m16n8k16 path (tcgen05 not available at harness's compute_103 target).

#define NROW 4096
#define DDIM 512
#define KTOT 8192            // hi (0..4095) || lo (4096..8191)
#define NKB 128              // kblocks of 64 bf16 (128 bytes)
#define NSTG 6               // ring of 6 stages, 2 kblocks consumed per sync
#define STG_B 32768          // A(16KB) + B(16KB)
#define SMEM_DYN (NSTG * STG_B + 1024)
#define PREP_ROWS 16
#define PREP_PITCH 516
#define PREP_SMEM (PREP_ROWS * PREP_PITCH * 4)

__device__ __nv_bfloat16 g_tp[4][(size_t)DDIM * KTOT]; // [d][k], K-major
__device__ float g_acc;

// ---------------- PTX helpers ----------------
__device__ __forceinline__ uint32_t s2u(const void* p) {
    uint32_t a;
    asm("{ .reg .u64 t; cvta.to.shared.u64 t, %1; cvt.u32.u64 %0, t; }" : "=r"(a) : "l"(p));
    return a;
}
__device__ __forceinline__ void cp16(uint32_t dst, const void* src) {
    asm volatile("cp.async.cg.shared.global [%0], [%1], 16;" :: "r"(dst), "l"(src) : "memory");
}
#define CP_COMMIT() asm volatile("cp.async.commit_group;" ::: "memory")
#define CP_WAIT(n)  asm volatile("cp.async.wait_group %0;" :: "n"(n) : "memory")

__device__ __forceinline__ void ldsm4(uint32_t* r, uint32_t addr) {
    asm volatile("ldmatrix.sync.aligned.m8n8.x4.shared.b16 {%0,%1,%2,%3}, [%4];"
                 : "=r"(r[0]), "=r"(r[1]), "=r"(r[2]), "=r"(r[3]) : "r"(addr));
}
__device__ __forceinline__ void mma16816(float* d, const uint32_t* a, const uint32_t* b) {
    asm volatile(
        "mma.sync.aligned.m16n8k16.row.col.f32.bf16.bf16.f32 "
        "{%0,%1,%2,%3}, {%4,%5,%6,%7}, {%8,%9}, {%0,%1,%2,%3};"
        : "+f"(d[0]), "+f"(d[1]), "+f"(d[2]), "+f"(d[3])
        : "r"(a[0]), "r"(a[1]), "r"(a[2]), "r"(a[3]), "r"(b[0]), "r"(b[1]));
}

// ---------------- finalize ----------------
__global__ void finalize_kernel(float* out) {
    out[0] = g_acc * (100.0f / (4096.0f * 4096.0f));
}

// ---------------- fused normalize + transpose + bf16 hi/lo split ----------------
// grid (4096/16, 4), 256 threads; block holds 16 rows (16x512 fp32, 33KB) in SMEM.
__global__ void __launch_bounds__(256, 1) prep_kernel(
    const float* __restrict__ i0, const float* __restrict__ i1,
    const float* __restrict__ i2, const float* __restrict__ i3) {
    const float* ins[4] = {i0, i1, i2, i3};
    const int mod = blockIdx.y;
    const float* in = ins[mod];
    __nv_bfloat16* out = g_tp[mod];
    const int r0 = blockIdx.x * PREP_ROWS;
    const int tid = threadIdx.x;

    if (blockIdx.x == 0 && mod == 0 && tid == 0) g_acc = 0.0f;

    extern __shared__ float ptile[];   // [16][516]
    __shared__ float rnorm[PREP_ROWS];

    // load 16 rows x 512 fp32 (each row = 128 float4)
    for (int i = tid; i < PREP_ROWS * 128; i += 256) {
        int r = i >> 7, c = i & 127;
        float4 v = ((const float4*)(in + (size_t)(r0 + r) * DDIM))[c];
        *(float4*)&ptile[r * PREP_PITCH + c * 4] = v;
    }
    __syncthreads();

    // per-row inverse L2 norm: warp w handles rows w, w+8
    {
        int w = tid >> 5, lane = tid & 31;
        for (int r = w; r < PREP_ROWS; r += 8) {
            const float* row = &ptile[r * PREP_PITCH];
            float s = 0.0f;
#pragma unroll
            for (int k = 0; k < 16; ++k) {
                float v = row[lane + 32 * k];
                s += v * v;
            }
#pragma unroll
            for (int o = 16; o; o >>= 1) s += __shfl_xor_sync(0xffffffffu, s, o);
            if (lane == 0) rnorm[r] = rsqrtf(fmaxf(s, 1e-24f));
        }
    }
    __syncthreads();

    // transpose + hi/lo split, 4 chunks of 128 dims
    const int il = tid >> 1;            // 0..127 (dim within chunk)
    const int rs = (tid & 1) * 8;       // rows 0..7 or 8..15
    for (int c4 = 0; c4 < 4; ++c4) {
        const int ib = c4 * 128;
        __align__(16) __nv_bfloat16 hi[8], lo[8];
#pragma unroll
        for (int j = 0; j < 8; ++j) {
            float v = ptile[(rs + j) * PREP_PITCH + ib + il] * rnorm[rs + j];
            __nv_bfloat16 h = __float2bfloat16(v);
            hi[j] = h;
            lo[j] = __float2bfloat16(v - __bfloat162float(h));
        }
        size_t ob = (size_t)(ib + il) * KTOT + r0 + rs;
        *(uint4*)(out + ob) = *(const uint4*)&hi[0];
        *(uint4*)(out + ob + 4096) = *(const uint4*)&lo[0];
    }
}

// ---------------- HMMA GEMM + Frobenius ----------------
// grid (4,4,7), 512 threads = 16 warps (4x4), warp tile 32x32.
// 6-stage cp.async ring, 2 kblocks per __syncthreads, register-level
// double-buffered fragments (ldsm for ks+1 overlaps mma for ks).
__global__ void __launch_bounds__(512, 1) gemmfro_kernel() {
    const int ta[7] = {3, 0, 1, 2, 3, 3, 3};
    const int tb[7] = {3, 0, 1, 2, 0, 1, 2};
    const float tw[7] = {3.0f, 1.0f, 1.0f, 1.0f, -2.0f, -2.0f, -2.0f};

    extern __shared__ __align__(16) char dsm[];
    __shared__ float red[16];

    const int tid = threadIdx.x;
    const int wid = tid >> 5;
    const int lane = tid & 31;
    const int wm = wid & 3;
    const int wn = wid >> 2;

    uint32_t smem0 = (s2u(dsm) + 1023u) & ~1023u;

    const int task = blockIdx.z;
    const __nv_bfloat16* A = g_tp[ta[task]];
    const __nv_bfloat16* B = g_tp[tb[task]];
    const int I = blockIdx.x * 128;
    const int J = blockIdx.y * 128;

    // cp.async mapping: 512 threads cover 256 rows x 128B; thread owns half a row
    const int lrow = tid >> 1;
    const int cb = (tid & 1) * 4;
    const __nv_bfloat16* gsrc = (lrow < 128)
        ? (A + (size_t)(I + lrow) * KTOT)
        : (B + (size_t)(J + lrow - 128) * KTOT);
    const char* srow = (const char*)gsrc;
    uint32_t soff[4];
#pragma unroll
    for (int c = 0; c < 4; ++c)
        soff[c] = (uint32_t)lrow * 128 + (uint32_t)(((cb + c) * 16) ^ ((lrow & 7) * 16));

    auto load_stage = [&](int kb) {
        uint32_t base = smem0 + (uint32_t)(kb % NSTG) * STG_B;
        const char* g = srow + (size_t)kb * 128;
#pragma unroll
        for (int c = 0; c < 4; ++c) cp16(base + soff[c], g + (cb + c) * 16);
    };

    // ldmatrix lane address precompute (warp tile 32x32)
    const int m0 = wm * 32, n0 = wn * 32;
    uint32_t aoff[2], axr[2], boff[2], bxr[2];
#pragma unroll
    for (int i = 0; i < 2; ++i) {
        int r = m0 + i * 16 + ((lane >> 3) & 1) * 8 + (lane & 7);
        aoff[i] = (uint32_t)r * 128;
        axr[i] = (uint32_t)(r & 7) * 16;
    }
#pragma unroll
    for (int jp = 0; jp < 2; ++jp) {
        int r = n0 + jp * 16 + ((lane >> 4) & 1) * 8 + (lane & 7);
        boff[jp] = (uint32_t)r * 128;
        bxr[jp] = (uint32_t)(r & 7) * 16;
    }
    const uint32_t ah = (uint32_t)(lane >> 4) * 16;
    const uint32_t bh = (uint32_t)((lane >> 3) & 1) * 16;

    float acc[2][4][4];
#pragma unroll
    for (int i = 0; i < 2; ++i)
#pragma unroll
        for (int j = 0; j < 4; ++j)
#pragma unroll
            for (int r = 0; r < 4; ++r) acc[i][j][r] = 0.0f;

    // double-buffered fragments
    uint32_t af[2][2][4], bf[2][2][4];

    auto frag_load = [&](int buf, uint32_t sa, int ks) {
        uint32_t sb = sa + 16384;
        uint32_t ko = (uint32_t)(ks * 32);
        ldsm4(af[buf][0], sa + aoff[0] + ((ko + ah) ^ axr[0]));
        ldsm4(af[buf][1], sa + aoff[1] + ((ko + ah) ^ axr[1]));
        ldsm4(bf[buf][0], sb + boff[0] + ((ko + bh) ^ bxr[0]));
        ldsm4(bf[buf][1], sb + boff[1] + ((ko + bh) ^ bxr[1]));
    };
    auto frag_mma = [&](int buf) {
#pragma unroll
        for (int i = 0; i < 2; ++i)
#pragma unroll
            for (int jp = 0; jp < 2; ++jp) {
                mma16816(acc[i][2 * jp + 0], af[buf][i], &bf[buf][jp][0]);
                mma16816(acc[i][2 * jp + 1], af[buf][i], &bf[buf][jp][2]);
            }
    };

    // prologue: 4 stages in flight; first fragments preloaded
    load_stage(0); CP_COMMIT();
    load_stage(1); CP_COMMIT();
    load_stage(2); CP_COMMIT();
    load_stage(3); CP_COMMIT();
    CP_WAIT(2);
    __syncthreads();
    frag_load(0, smem0, 0);

    for (int kb = 0; kb < NKB; kb += 2) {
        if (kb + 4 < NKB) { load_stage(kb + 4); CP_COMMIT(); }
        if (kb + 5 < NKB) { load_stage(kb + 5); CP_COMMIT(); }

        uint32_t sa0 = smem0 + (uint32_t)(kb % NSTG) * STG_B;
        uint32_t sa1 = smem0 + (uint32_t)((kb + 1) % NSTG) * STG_B;

        // 8 ks-steps across the pair; mma on buf t&1 while loading buf (t+1)&1
#pragma unroll
        for (int t = 0; t < 8; ++t) {
            if (t < 7) {
                const int nt = t + 1;
                frag_load(nt & 1, (nt >> 2) ? sa1 : sa0, nt & 3);
            }
            frag_mma(t & 1);
        }

        if (kb + 2 < NKB) {
            CP_WAIT(2);                 // stages kb+2, kb+3 resident
            __syncthreads();            // all warps done with kb, kb+1
            frag_load(0, smem0 + (uint32_t)((kb + 2) % NSTG) * STG_B, 0);
        }
    }

    // Frobenius of this warp's 32x32 block
    float s = 0.0f;
#pragma unroll
    for (int i = 0; i < 2; ++i)
#pragma unroll
        for (int j = 0; j < 4; ++j)
#pragma unroll
            for (int r = 0; r < 4; ++r) s += acc[i][j][r] * acc[i][j][r];
#pragma unroll
    for (int o = 16; o; o >>= 1) s += __shfl_xor_sync(0xffffffffu, s, o);
    if (lane == 0) red[wid] = s;
    __syncthreads();
    if (tid == 0) {
        float bs = red[0];
#pragma unroll
        for (int w = 1; w < 16; ++w) bs += red[w];
        atomicAdd(&g_acc, tw[task] * bs);
    }
}

extern "C" void kernel_launch(void* const* d_in, const int* in_sizes, int n_in,
                              void* d_out, int out_size) {
    const float* rgb   = (const float*)d_in[0];
    const float* depth = (const float*)d_in[1];
    const float* ir    = (const float*)d_in[2];
    const float* t     = (const float*)d_in[3];
    float* out = (float*)d_out;

    cudaFuncSetAttribute(prep_kernel, cudaFuncAttributeMaxDynamicSharedMemorySize, PREP_SMEM);
    cudaFuncSetAttribute(gemmfro_kernel, cudaFuncAttributeMaxDynamicSharedMemorySize, SMEM_DYN);

    prep_kernel<<<dim3(NROW / PREP_ROWS, 4, 1), 256, PREP_SMEM>>>(rgb, depth, ir, t);
    gemmfro_kernel<<<dim3(4, 4, 7), 512, SMEM_DYN>>>();
    finalize_kernel<<<1, 1>>>(out);
}